// round 2
// baseline (speedup 1.0000x reference)
#include <cuda_runtime.h>
#include <cuda_bf16.h>

#define BB   8
#define CIN  256
#define HL   64
#define WL   64
#define CMID 64
#define HHI  128
#define WHI  128
#define HP   136   // padded hi-res (pad 4 each side)
#define EPSV 1e-5f

// ------------------------- device scratch -------------------------
__device__ float g_WT[CIN * CMID];              // folded transposed 1x1 weights [k][co]
__device__ float g_bias1[CMID];
__device__ float g_EWr[576 * 112];              // folded enc weights [k=cin*9+dy*3+dx][q*28+kk] (cout=q+4kk)
__device__ float g_bias2r[112];                 // [q*28+kk]
__device__ float g_W1[BB * CMID * HL * WL];     // conv1 output (8,64,64,64)
__device__ float g_Wsm[BB * HHI * WHI * 25];    // softmaxed weights, [b][y][x][25]
__device__ float g_Xu[(size_t)BB * CIN * HP * HP]; // padded bilinear upsample

// ------------------------- K0: fold BN into weights -------------------------
__global__ void k0_prep(const float* __restrict__ comp_w, const float* __restrict__ comp_b,
                        const float* __restrict__ g1, const float* __restrict__ b1,
                        const float* __restrict__ m1, const float* __restrict__ v1,
                        const float* __restrict__ enc_w, const float* __restrict__ enc_b,
                        const float* __restrict__ g2, const float* __restrict__ b2,
                        const float* __restrict__ m2, const float* __restrict__ v2) {
    int idx = blockIdx.x * 256 + threadIdx.x;
    if (idx < CIN * CMID) {                      // transposed, scaled 1x1 weights
        int k = idx / CMID, co = idx % CMID;
        float s = g1[co] * rsqrtf(v1[co] + EPSV);
        g_WT[idx] = comp_w[co * CIN + k] * s;
    }
    if (idx < CMID) {
        float s = g1[idx] * rsqrtf(v1[idx] + EPSV);
        g_bias1[idx] = s * (comp_b[idx] - m1[idx]) + b1[idx];
    }
    if (idx < 576 * 112) {                       // enc weights reordered for K2
        int k = idx / 112, r = idx % 112;
        int q = r / 28, kk = r % 28;
        float val = 0.f;
        if (kk < 25) {
            int cout = q + 4 * kk;
            float s = g2[cout] * rsqrtf(v2[cout] + EPSV);
            val = enc_w[cout * 576 + k] * s;
        }
        g_EWr[idx] = val;
    }
    if (idx < 112) {
        int q = idx / 28, kk = idx % 28;
        float val = 0.f;
        if (kk < 25) {
            int cout = q + 4 * kk;
            float s = g2[cout] * rsqrtf(v2[cout] + EPSV);
            val = s * (enc_b[cout] - m2[cout]) + b2[cout];
        }
        g_bias2r[idx] = val;
    }
}

// ------------------------- K1: 1x1 conv GEMM + bias + relu -------------------------
// block: 256 thr, tile 64 cout x 128 px, K=256 in chunks of 16. thread: 8 cout x 4 px.
__global__ __launch_bounds__(256) void k1_conv1(const float* __restrict__ X) {
    __shared__ __align__(16) float Xs[16][128];
    __shared__ __align__(16) float Wts[16][64];
    int tid = threadIdx.x;
    int r = tid >> 5;                  // cout group 0..7
    int c = tid & 31;                  // px group 0..31
    int b = blockIdx.y;
    int p0 = blockIdx.x * 128;
    const float* Xb = X + (size_t)b * CIN * HL * WL;

    float acc[8][4];
#pragma unroll
    for (int i = 0; i < 8; i++)
#pragma unroll
        for (int j = 0; j < 4; j++) acc[i][j] = 0.f;

    for (int k0 = 0; k0 < CIN; k0 += 16) {
        __syncthreads();
#pragma unroll
        for (int i = tid; i < 512; i += 256) {
            int kk = i >> 5, pp = (i & 31) * 4;
            *(float4*)&Xs[kk][pp] = *(const float4*)&Xb[(size_t)(k0 + kk) * (HL * WL) + p0 + pp];
        }
        {
            int kk = tid >> 4, co = (tid & 15) * 4;
            *(float4*)&Wts[kk][co] = *(const float4*)&g_WT[(k0 + kk) * CMID + co];
        }
        __syncthreads();
#pragma unroll
        for (int kk = 0; kk < 16; kk++) {
            float a[8], x[4];
            *(float4*)&a[0] = *(float4*)&Wts[kk][r * 8];
            *(float4*)&a[4] = *(float4*)&Wts[kk][r * 8 + 4];
            *(float4*)&x[0] = *(float4*)&Xs[kk][c * 4];
#pragma unroll
            for (int i = 0; i < 8; i++)
#pragma unroll
                for (int j = 0; j < 4; j++) acc[i][j] = fmaf(a[i], x[j], acc[i][j]);
        }
    }
#pragma unroll
    for (int i = 0; i < 8; i++) {
        int co = r * 8 + i;
        float bs = g_bias1[co];
        float4 v;
        v.x = fmaxf(acc[i][0] + bs, 0.f);
        v.y = fmaxf(acc[i][1] + bs, 0.f);
        v.z = fmaxf(acc[i][2] + bs, 0.f);
        v.w = fmaxf(acc[i][3] + bs, 0.f);
        *(float4*)&g_W1[((size_t)b * CMID + co) * (HL * WL) + p0 + c * 4] = v;
    }
}

// ------------------------- K2: 3x3 conv (64->100) + bn2 + pixel-shuffle softmax -----
// block: 128 thr, low-res tile 8x8. thread: q = tid&3 (softmax group), 2 x-adjacent pixels.
__global__ __launch_bounds__(128) void k2_kernelpred() {
    __shared__ __align__(16) float tin[4][10][10];    // input tile chunk (4 cin)
    __shared__ __align__(16) float twt[36][112];      // weight chunk
    int tid = threadIdx.x;
    int q = tid & 3;
    int p0 = (tid >> 2) * 2;                          // even pixel index in 8x8 tile
    int py = p0 >> 3, px = p0 & 7;                    // p0, p0+1 share a row
    int b = blockIdx.y;
    int y0 = (blockIdx.x >> 3) * 8, x0 = (blockIdx.x & 7) * 8;

    float bb[28];
#pragma unroll
    for (int i = 0; i < 7; i++)
        *(float4*)&bb[i * 4] = *(const float4*)&g_bias2r[q * 28 + i * 4];
    float a0[25], a1[25];
#pragma unroll
    for (int t = 0; t < 25; t++) { a0[t] = bb[t]; a1[t] = bb[t]; }

    for (int ch = 0; ch < 16; ch++) {                 // 16 chunks of 4 cin
        int cin0 = ch * 4;
        __syncthreads();
        for (int l = tid; l < 400; l += 128) {        // stage input tile (zero-padded)
            int cin = l / 100, rem = l % 100;
            int ty = rem / 10, tx = rem % 10;
            int gy = y0 + ty - 1, gx = x0 + tx - 1;
            float v = 0.f;
            if (gy >= 0 && gy < HL && gx >= 0 && gx < WL)
                v = g_W1[((size_t)(b * CMID + cin0 + cin) * HL + gy) * WL + gx];
            tin[cin][ty][tx] = v;
        }
        {
            const float4* src = (const float4*)&g_EWr[ch * 36 * 112];
            float4* dst = (float4*)&twt[0][0];
            for (int i = tid; i < 1008; i += 128) dst[i] = src[i];
        }
        __syncthreads();
#pragma unroll
        for (int cin = 0; cin < 4; cin++)
#pragma unroll
            for (int dy = 0; dy < 3; dy++)
#pragma unroll
                for (int dx = 0; dx < 3; dx++) {
                    int kl = cin * 9 + dy * 3 + dx;
                    float x0v = tin[cin][py + dy][px + dx];
                    float x1v = tin[cin][py + dy][px + dx + 1];
                    float w[28];
#pragma unroll
                    for (int i = 0; i < 7; i++)
                        *(float4*)&w[i * 4] = *(const float4*)&twt[kl][q * 28 + i * 4];
#pragma unroll
                    for (int t = 0; t < 25; t++) {
                        a0[t] = fmaf(w[t], x0v, a0[t]);
                        a1[t] = fmaf(w[t], x1v, a1[t]);
                    }
                }
    }

    // softmax over 25, write to [b][Y][X][25]
    int ry = q >> 1, rx = q & 1;
    int Y = 2 * (y0 + py) + ry;
#pragma unroll
    for (int pix = 0; pix < 2; pix++) {
        float* a = pix ? a1 : a0;
        int X = 2 * (x0 + px + pix) + rx;
        float m = a[0];
#pragma unroll
        for (int t = 1; t < 25; t++) m = fmaxf(m, a[t]);
        float s = 0.f;
#pragma unroll
        for (int t = 0; t < 25; t++) { a[t] = __expf(a[t] - m); s += a[t]; }
        float inv = 1.0f / s;
        float* dst = &g_Wsm[((size_t)(b * HHI + Y) * WHI + X) * 25];
#pragma unroll
        for (int t = 0; t < 25; t++) dst[t] = a[t] * inv;
    }
}

// ------------------------- K_bil: bilinear x2 upsample into padded scratch ---------
__global__ __launch_bounds__(256) void k_bilinear(const float* __restrict__ X) {
    int gid = blockIdx.x * 256 + threadIdx.x;     // one float4 (4 xp) per thread
    int xq = gid % 34; int t = gid / 34;
    int yp = t % HP;  t /= HP;
    int c = t % CIN;  int b = t / CIN;
    int y = yp - 4;
    float4 v = make_float4(0.f, 0.f, 0.f, 0.f);
    float* out = &g_Xu[(((size_t)(b * CIN + c) * HP) + yp) * HP + xq * 4];
    if (y >= 0 && y < HHI) {
        int ry = y & 1, yl = y >> 1;
        int ya, yb; float wya, wyb;
        if (ry == 0) { ya = max(yl - 1, 0); yb = yl; wya = 0.25f; wyb = 0.75f; }
        else         { ya = yl; yb = min(yl + 1, HL - 1); wya = 0.75f; wyb = 0.25f; }
        const float* ra = X + ((size_t)(b * CIN + c) * HL + ya) * WL;
        const float* rb = X + ((size_t)(b * CIN + c) * HL + yb) * WL;
        float* vp = (float*)&v;
#pragma unroll
        for (int u = 0; u < 4; u++) {
            int x = xq * 4 + u - 4;
            if (x >= 0 && x < WHI) {
                int rx = x & 1, xl = x >> 1;
                int xa, xb; float wxa, wxb;
                if (rx == 0) { xa = max(xl - 1, 0); xb = xl; wxa = 0.25f; wxb = 0.75f; }
                else         { xa = xl; xb = min(xl + 1, WL - 1); wxa = 0.75f; wxb = 0.25f; }
                vp[u] = wya * (wxa * __ldg(ra + xa) + wxb * __ldg(ra + xb)) +
                        wyb * (wxa * __ldg(rb + xa) + wxb * __ldg(rb + xb));
            }
        }
    }
    *(float4*)out = v;
}

// ------------------------- K3: weighted reassembly ---------------------------------
// block 128 thr: 4 rows x 32 quads (full 128-wide row), grid (32, 8, 2 ch halves).
// thread: 4 x-pixels, 100 weight regs, loops 128 channels.
__global__ __launch_bounds__(128) void k3_reassemble(float* __restrict__ out) {
    int tid = threadIdx.x;
    int y = blockIdx.x * 4 + (tid >> 5);
    int x4 = (tid & 31) * 4;
    int b = blockIdx.y;
    int c0 = blockIdx.z * 128;

    float w[4][25];
    const float* wb = &g_Wsm[((size_t)(b * HHI + y) * WHI + x4) * 25];
#pragma unroll
    for (int u = 0; u < 4; u++)
#pragma unroll
        for (int k = 0; k < 25; k++) w[u][k] = __ldg(wb + u * 25 + k);

    const float* xu = &g_Xu[(((size_t)(b * CIN + c0) * HP) + y) * HP + x4];
    float* ob = out + ((size_t)(b * CIN + c0) * HHI + y) * WHI + x4;

    for (int c = 0; c < 128; c++) {
        const float* xr = xu + (size_t)c * HP * HP;
        float acc0 = 0.f, acc1 = 0.f, acc2 = 0.f, acc3 = 0.f;
#pragma unroll
        for (int i = 0; i < 5; i++) {
            float4 A = *(const float4*)(xr + 2 * i * HP);
            float4 B = *(const float4*)(xr + 2 * i * HP + 4);
            float4 C = *(const float4*)(xr + 2 * i * HP + 8);
            float f[12] = {A.x, A.y, A.z, A.w, B.x, B.y, B.z, B.w, C.x, C.y, C.z, C.w};
#pragma unroll
            for (int j = 0; j < 5; j++) {
                acc0 = fmaf(w[0][i * 5 + j], f[0 + 2 * j], acc0);
                acc1 = fmaf(w[1][i * 5 + j], f[1 + 2 * j], acc1);
                acc2 = fmaf(w[2][i * 5 + j], f[2 + 2 * j], acc2);
                acc3 = fmaf(w[3][i * 5 + j], f[3 + 2 * j], acc3);
            }
        }
        *(float4*)(ob + (size_t)c * HHI * WHI) = make_float4(acc0, acc1, acc2, acc3);
    }
}

// ------------------------- launch -------------------------
extern "C" void kernel_launch(void* const* d_in, const int* in_sizes, int n_in,
                              void* d_out, int out_size) {
    const float* X      = (const float*)d_in[0];
    const float* comp_w = (const float*)d_in[1];
    const float* comp_b = (const float*)d_in[2];
    const float* bn1_g  = (const float*)d_in[3];
    const float* bn1_b  = (const float*)d_in[4];
    const float* bn1_m  = (const float*)d_in[5];
    const float* bn1_v  = (const float*)d_in[6];
    const float* enc_w  = (const float*)d_in[7];
    const float* enc_b  = (const float*)d_in[8];
    const float* bn2_g  = (const float*)d_in[9];
    const float* bn2_b  = (const float*)d_in[10];
    const float* bn2_m  = (const float*)d_in[11];
    const float* bn2_v  = (const float*)d_in[12];
    float* out = (float*)d_out;

    k0_prep<<<252, 256>>>(comp_w, comp_b, bn1_g, bn1_b, bn1_m, bn1_v,
                          enc_w, enc_b, bn2_g, bn2_b, bn2_m, bn2_v);
    k1_conv1<<<dim3(32, 8), 256>>>(X);
    k_bilinear<<<36992, 256>>>(X);
    k2_kernelpred<<<dim3(64, 8), 128>>>();
    k3_reassemble<<<dim3(32, 8, 2), 128>>>(out);
}

// round 4
// speedup vs baseline: 1.1313x; 1.1313x over previous
#include <cuda_runtime.h>
#include <cuda_bf16.h>

#define BB   8
#define CIN  256
#define HL   64
#define WL   64
#define CMID 64
#define HHI  128
#define WHI  128
#define HP   136   // padded hi-res (pad 4 each side)
#define EPSV 1e-5f

// ------------------------- device scratch -------------------------
__device__ float g_WT[CIN * CMID];              // folded transposed 1x1 weights [k][co]
__device__ float g_bias1[CMID];
__device__ float g_EWr[576 * 112];              // folded enc weights [k=cin*9+dy*3+dx][m=q*28+kk] (cout=q+4kk)
__device__ float g_bias2r[112];                 // [q*28+kk]
__device__ float g_W1[BB * CMID * HL * WL];     // conv1 output (8,64,64,64)
__device__ float g_Wsm[BB * HHI * WHI * 25];    // softmaxed weights, [b][y][x][25]
__device__ float g_Xu[(size_t)BB * CIN * HP * HP]; // padded bilinear upsample

// packed fp32x2 FMA (bit-exact 2x fp32 fma, Blackwell fp32x2 pipe)
__device__ __forceinline__ void ffma2(float2& c, float2 a, float2 b) {
    asm("fma.rn.f32x2 %0, %1, %2, %0;"
        : "+l"(reinterpret_cast<unsigned long long&>(c))
        : "l"(reinterpret_cast<unsigned long long&>(a)),
          "l"(reinterpret_cast<unsigned long long&>(b)));
}

// ------------------------- K0: fold BN into weights -------------------------
__global__ void k0_prep(const float* __restrict__ comp_w, const float* __restrict__ comp_b,
                        const float* __restrict__ g1, const float* __restrict__ b1,
                        const float* __restrict__ m1, const float* __restrict__ v1,
                        const float* __restrict__ enc_w, const float* __restrict__ enc_b,
                        const float* __restrict__ g2, const float* __restrict__ b2,
                        const float* __restrict__ m2, const float* __restrict__ v2) {
    int idx = blockIdx.x * 256 + threadIdx.x;
    if (idx < CIN * CMID) {                      // transposed, scaled 1x1 weights
        int k = idx / CMID, co = idx % CMID;
        float s = g1[co] * rsqrtf(v1[co] + EPSV);
        g_WT[idx] = comp_w[co * CIN + k] * s;
    }
    if (idx < CMID) {
        float s = g1[idx] * rsqrtf(v1[idx] + EPSV);
        g_bias1[idx] = s * (comp_b[idx] - m1[idx]) + b1[idx];
    }
    if (idx < 576 * 112) {                       // enc weights reordered for K2
        int k = idx / 112, r = idx % 112;
        int q = r / 28, kk = r % 28;
        float val = 0.f;
        if (kk < 25) {
            int cout = q + 4 * kk;
            float s = g2[cout] * rsqrtf(v2[cout] + EPSV);
            val = enc_w[cout * 576 + k] * s;
        }
        g_EWr[idx] = val;
    }
    if (idx < 112) {
        int q = idx / 28, kk = idx % 28;
        float val = 0.f;
        if (kk < 25) {
            int cout = q + 4 * kk;
            float s = g2[cout] * rsqrtf(v2[cout] + EPSV);
            val = s * (enc_b[cout] - m2[cout]) + b2[cout];
        }
        g_bias2r[idx] = val;
    }
}

// ------------------------- K1: 1x1 conv GEMM + bias + relu (f32x2) ----------------
// block: 256 thr, tile 64 cout x 128 px, K=256 in chunks of 16. thread: 8 cout x 4 px.
__global__ __launch_bounds__(256) void k1_conv1(const float* __restrict__ X) {
    __shared__ __align__(16) float Xs[16][128];
    __shared__ __align__(16) float Wts[16][64];
    int tid = threadIdx.x;
    int r = tid >> 5;                  // cout group 0..7
    int c = tid & 31;                  // px group 0..31
    int b = blockIdx.y;
    int p0 = blockIdx.x * 128;
    const float* Xb = X + (size_t)b * CIN * HL * WL;

    float2 acc2[4][4];                 // [m-pair][px]
#pragma unroll
    for (int i = 0; i < 4; i++)
#pragma unroll
        for (int j = 0; j < 4; j++) acc2[i][j] = make_float2(0.f, 0.f);

    for (int k0 = 0; k0 < CIN; k0 += 16) {
        __syncthreads();
#pragma unroll
        for (int i = tid; i < 512; i += 256) {
            int kk = i >> 5, pp = (i & 31) * 4;
            *(float4*)&Xs[kk][pp] = *(const float4*)&Xb[(size_t)(k0 + kk) * (HL * WL) + p0 + pp];
        }
        {
            int kk = tid >> 4, co = (tid & 15) * 4;
            *(float4*)&Wts[kk][co] = *(const float4*)&g_WT[(k0 + kk) * CMID + co];
        }
        __syncthreads();
#pragma unroll
        for (int kk = 0; kk < 16; kk++) {
            float2 w2[4]; float x[4];
            *(float4*)&w2[0] = *(float4*)&Wts[kk][r * 8];
            *(float4*)&w2[2] = *(float4*)&Wts[kk][r * 8 + 4];
            *(float4*)&x[0] = *(float4*)&Xs[kk][c * 4];
            float2 xd[4];
#pragma unroll
            for (int j = 0; j < 4; j++) xd[j] = make_float2(x[j], x[j]);
#pragma unroll
            for (int i = 0; i < 4; i++)
#pragma unroll
                for (int j = 0; j < 4; j++) ffma2(acc2[i][j], w2[i], xd[j]);
        }
    }
#pragma unroll
    for (int i = 0; i < 4; i++) {
        int co0 = r * 8 + 2 * i;
        float b0 = g_bias1[co0], b1 = g_bias1[co0 + 1];
        float4 v0, v1;
        v0.x = fmaxf(acc2[i][0].x + b0, 0.f); v0.y = fmaxf(acc2[i][1].x + b0, 0.f);
        v0.z = fmaxf(acc2[i][2].x + b0, 0.f); v0.w = fmaxf(acc2[i][3].x + b0, 0.f);
        v1.x = fmaxf(acc2[i][0].y + b1, 0.f); v1.y = fmaxf(acc2[i][1].y + b1, 0.f);
        v1.z = fmaxf(acc2[i][2].y + b1, 0.f); v1.w = fmaxf(acc2[i][3].y + b1, 0.f);
        *(float4*)&g_W1[((size_t)b * CMID + co0) * (HL * WL) + p0 + c * 4] = v0;
        *(float4*)&g_W1[((size_t)b * CMID + co0 + 1) * (HL * WL) + p0 + c * 4] = v1;
    }
}

// ------------------------- K2: 3x3 conv as tiled GEMM + softmax epilogue ----------
// GEMM: M=112 (couts, m=q*28+kk), N=128 px tile (8 rows x 16 cols), K=576.
// 256 thr: mg=tid>>4 owns 7 couts, ng=tid&15 owns 8 consecutive x in one row.
// Register-shift: load 10-float row once per (cin,dy), reuse for dx=0..2.
__global__ __launch_bounds__(256) void k2_kernelpred() {
    __shared__ __align__(16) float smem[7392];   // mainloop: tin[4][10][20]+twt[36][112]=4832; epi: sL[112][66]=7392
    float* tin = smem;          // [cin][ty][tx] stride 200/20
    float* twt = smem + 800;    // [36][112]

    int tid = threadIdx.x;
    int mg = tid >> 4;                        // 0..15 -> couts mg*7..mg*7+6
    int ng = tid & 15;
    int py = ng >> 1;                         // row in 8-row tile
    int px0 = (ng & 1) * 8;                   // col start (0 or 8) in 16-col tile
    int b = blockIdx.y;
    int y0 = (blockIdx.x >> 2) * 8;
    int x0 = (blockIdx.x & 3) * 16;

    float2 acc[7][4];
#pragma unroll
    for (int i = 0; i < 7; i++)
#pragma unroll
        for (int j = 0; j < 4; j++) acc[i][j] = make_float2(0.f, 0.f);

    for (int ch = 0; ch < 16; ch++) {
        __syncthreads();
        for (int l = tid; l < 720; l += 256) {           // stage input tile 4x10x18
            int cin = l / 180, rem = l % 180;
            int ty = rem / 18, tx = rem % 18;
            int gy = y0 + ty - 1, gx = x0 + tx - 1;
            float v = 0.f;
            if (gy >= 0 && gy < HL && gx >= 0 && gx < WL)
                v = g_W1[(((size_t)b * CMID + ch * 4 + cin) * HL + gy) * WL + gx];
            tin[cin * 200 + ty * 20 + tx] = v;
        }
        {                                                 // stage weights 36x112
            const float4* src = (const float4*)(g_EWr + ch * 4032);
            float4* dst = (float4*)twt;
            for (int i = tid; i < 1008; i += 256) dst[i] = src[i];
        }
        __syncthreads();
#pragma unroll
        for (int cin = 0; cin < 4; cin++)
#pragma unroll
            for (int dy = 0; dy < 3; dy++) {
                const float* rp = &tin[cin * 200 + (py + dy) * 20 + px0];
                float r[10];
                *(float4*)&r[0] = *(const float4*)rp;
                *(float4*)&r[4] = *(const float4*)(rp + 4);
                *(float2*)&r[8] = *(const float2*)(rp + 8);
#pragma unroll
                for (int dx = 0; dx < 3; dx++) {
                    int kl = cin * 9 + dy * 3 + dx;
                    const float* wp = &twt[kl * 112 + mg * 7];
#pragma unroll
                    for (int i = 0; i < 7; i++) {
                        float w = wp[i];
                        float2 w2 = make_float2(w, w);
#pragma unroll
                        for (int j = 0; j < 4; j++) {
                            float2 x2 = make_float2(r[dx + 2 * j], r[dx + 2 * j + 1]);
                            ffma2(acc[i][j], w2, x2);
                        }
                    }
                }
            }
    }

    // epilogue: transpose via smem (two x-halves), bias + pixel-shuffle softmax
    float* sL = smem;                                     // [112][66]
    for (int half = 0; half < 2; half++) {
        __syncthreads();
        if ((ng & 1) == half) {
            int colb = py * 8;
#pragma unroll
            for (int i = 0; i < 7; i++) {
                float* row = &sL[(mg * 7 + i) * 66 + colb];
#pragma unroll
                for (int j = 0; j < 4; j++) {
                    row[2 * j] = acc[i][j].x;
                    row[2 * j + 1] = acc[i][j].y;
                }
            }
        }
        __syncthreads();
        {
            int q = tid >> 6;                             // softmax group 0..3
            int pp = tid & 63;                            // pixel within half
            int pyy = pp >> 3, pxx = pp & 7;
            int yl = y0 + pyy, xl = x0 + half * 8 + pxx;
            float a[25];
            float mx = -1e30f;
#pragma unroll
            for (int kk = 0; kk < 25; kk++) {
                a[kk] = sL[(q * 28 + kk) * 66 + pp] + __ldg(&g_bias2r[q * 28 + kk]);
                mx = fmaxf(mx, a[kk]);
            }
            float s = 0.f;
#pragma unroll
            for (int kk = 0; kk < 25; kk++) { a[kk] = __expf(a[kk] - mx); s += a[kk]; }
            float inv = 1.0f / s;
            int Y = 2 * yl + (q >> 1), X = 2 * xl + (q & 1);
            float* dst = &g_Wsm[((size_t)(b * HHI + Y) * WHI + X) * 25];
#pragma unroll
            for (int kk = 0; kk < 25; kk++) dst[kk] = a[kk] * inv;
        }
    }
}

// ------------------------- K_bil: bilinear x2 upsample into padded scratch ---------
__global__ __launch_bounds__(256) void k_bilinear(const float* __restrict__ X) {
    int gid = blockIdx.x * 256 + threadIdx.x;     // one float4 (4 xp) per thread
    int xq = gid % 34; int t = gid / 34;
    int yp = t % HP;  t /= HP;
    int c = t % CIN;  int b = t / CIN;
    int y = yp - 4;
    float4 v = make_float4(0.f, 0.f, 0.f, 0.f);
    float* out = &g_Xu[(((size_t)(b * CIN + c) * HP) + yp) * HP + xq * 4];
    if (y >= 0 && y < HHI) {
        int ry = y & 1, yl = y >> 1;
        int ya, yb; float wya, wyb;
        if (ry == 0) { ya = max(yl - 1, 0); yb = yl; wya = 0.25f; wyb = 0.75f; }
        else         { ya = yl; yb = min(yl + 1, HL - 1); wya = 0.75f; wyb = 0.25f; }
        const float* ra = X + ((size_t)(b * CIN + c) * HL + ya) * WL;
        const float* rb = X + ((size_t)(b * CIN + c) * HL + yb) * WL;
        float* vp = (float*)&v;
#pragma unroll
        for (int u = 0; u < 4; u++) {
            int x = xq * 4 + u - 4;
            if (x >= 0 && x < WHI) {
                int rx = x & 1, xl = x >> 1;
                int xa, xb; float wxa, wxb;
                if (rx == 0) { xa = max(xl - 1, 0); xb = xl; wxa = 0.25f; wxb = 0.75f; }
                else         { xa = xl; xb = min(xl + 1, WL - 1); wxa = 0.75f; wxb = 0.25f; }
                vp[u] = wya * (wxa * __ldg(ra + xa) + wxb * __ldg(ra + xb)) +
                        wyb * (wxa * __ldg(rb + xa) + wxb * __ldg(rb + xb));
            }
        }
    }
    *(float4*)out = v;
}

// ------------------------- K3: weighted reassembly (f32x2, zero-repack pairs) ------
// block 128 thr: 4 rows x 32 quads, grid (32, 8, 2 ch halves). thread: 4 x-px, 128 ch.
__global__ __launch_bounds__(128) void k3_reassemble(float* __restrict__ out) {
    int tid = threadIdx.x;
    int y = blockIdx.x * 4 + (tid >> 5);
    int x4 = (tid & 31) * 4;
    int b = blockIdx.y;
    int c0 = blockIdx.z * 128;

    // weight pairs: wA[k]=(w_px0,w_px1), wB[k]=(w_px2,w_px3) — packed once
    float2 wA[25], wB[25];
    const float* wb = &g_Wsm[((size_t)(b * HHI + y) * WHI + x4) * 25];
#pragma unroll
    for (int k = 0; k < 25; k++) {
        wA[k] = make_float2(__ldg(wb + k),      __ldg(wb + 25 + k));
        wB[k] = make_float2(__ldg(wb + 50 + k), __ldg(wb + 75 + k));
    }

    const float* xu = &g_Xu[(((size_t)(b * CIN + c0) * HP) + y) * HP + x4];
    float* ob = out + ((size_t)(b * CIN + c0) * HHI + y) * WHI + x4;

    for (int c = 0; c < 128; c++) {
        const float* xr = xu + (size_t)c * HP * HP;
        float2 aP0 = make_float2(0.f, 0.f), aP1 = make_float2(0.f, 0.f);
#pragma unroll
        for (int i = 0; i < 5; i++) {
            float4 A = *(const float4*)(xr + 2 * i * HP);
            float4 B = *(const float4*)(xr + 2 * i * HP + 4);
            float4 C = *(const float4*)(xr + 2 * i * HP + 8);
            float2 pr[6] = { make_float2(A.x, A.y), make_float2(A.z, A.w),
                             make_float2(B.x, B.y), make_float2(B.z, B.w),
                             make_float2(C.x, C.y), make_float2(C.z, C.w) };
#pragma unroll
            for (int j = 0; j < 5; j++) {
                ffma2(aP0, wA[i * 5 + j], pr[j]);
                ffma2(aP1, wB[i * 5 + j], pr[j + 1]);
            }
        }
        *(float4*)(ob + (size_t)c * HHI * WHI) = make_float4(aP0.x, aP0.y, aP1.x, aP1.y);
    }
}

// ------------------------- launch -------------------------
extern "C" void kernel_launch(void* const* d_in, const int* in_sizes, int n_in,
                              void* d_out, int out_size) {
    const float* X      = (const float*)d_in[0];
    const float* comp_w = (const float*)d_in[1];
    const float* comp_b = (const float*)d_in[2];
    const float* bn1_g  = (const float*)d_in[3];
    const float* bn1_b  = (const float*)d_in[4];
    const float* bn1_m  = (const float*)d_in[5];
    const float* bn1_v  = (const float*)d_in[6];
    const float* enc_w  = (const float*)d_in[7];
    const float* enc_b  = (const float*)d_in[8];
    const float* bn2_g  = (const float*)d_in[9];
    const float* bn2_b  = (const float*)d_in[10];
    const float* bn2_m  = (const float*)d_in[11];
    const float* bn2_v  = (const float*)d_in[12];
    float* out = (float*)d_out;

    k0_prep<<<252, 256>>>(comp_w, comp_b, bn1_g, bn1_b, bn1_m, bn1_v,
                          enc_w, enc_b, bn2_g, bn2_b, bn2_m, bn2_v);
    k1_conv1<<<dim3(32, 8), 256>>>(X);
    k_bilinear<<<36992, 256>>>(X);
    k2_kernelpred<<<dim3(32, 8), 256>>>();
    k3_reassemble<<<dim3(32, 8, 2), 128>>>(out);
}

// round 5
// speedup vs baseline: 1.3352x; 1.1803x over previous
#include <cuda_runtime.h>
#include <cuda_bf16.h>

#define BB   8
#define CIN  256
#define HL   64
#define WL   64
#define CMID 64
#define HHI  128
#define WHI  128
#define HP   136   // padded hi-res (pad 4 each side)
#define EPSV 1e-5f

// ------------------------- device scratch -------------------------
__device__ float g_WT[CIN * CMID];              // folded transposed 1x1 weights [k][co]
__device__ float g_bias1[CMID];
__device__ float g_EWr[576 * 112];              // folded enc weights [k][m=q*28+kk] (cout=q+4kk)
__device__ float g_bias2r[112];                 // [q*28+kk]
__device__ float g_W1[BB * CMID * HL * WL];     // conv1 output (8,64,64,64)
__device__ float g_Wsm[BB * HHI * WHI * 25];    // softmaxed weights, [b][y][x][25]
__device__ float g_Xu[(size_t)BB * CIN * HP * HP]; // padded bilinear upsample

// packed fp32x2 FMA (bit-exact 2x fp32 fma)
__device__ __forceinline__ void ffma2(float2& c, float2 a, float2 b) {
    asm("fma.rn.f32x2 %0, %1, %2, %0;"
        : "+l"(reinterpret_cast<unsigned long long&>(c))
        : "l"(reinterpret_cast<unsigned long long&>(a)),
          "l"(reinterpret_cast<unsigned long long&>(b)));
}

// ------------------------- K0: fold BN into weights -------------------------
__global__ void k0_prep(const float* __restrict__ comp_w, const float* __restrict__ comp_b,
                        const float* __restrict__ g1, const float* __restrict__ b1,
                        const float* __restrict__ m1, const float* __restrict__ v1,
                        const float* __restrict__ enc_w, const float* __restrict__ enc_b,
                        const float* __restrict__ g2, const float* __restrict__ b2,
                        const float* __restrict__ m2, const float* __restrict__ v2) {
    int idx = blockIdx.x * 256 + threadIdx.x;
    if (idx < CIN * CMID) {
        int k = idx / CMID, co = idx % CMID;
        float s = g1[co] * rsqrtf(v1[co] + EPSV);
        g_WT[idx] = comp_w[co * CIN + k] * s;
    }
    if (idx < CMID) {
        float s = g1[idx] * rsqrtf(v1[idx] + EPSV);
        g_bias1[idx] = s * (comp_b[idx] - m1[idx]) + b1[idx];
    }
    if (idx < 576 * 112) {
        int k = idx / 112, r = idx % 112;
        int q = r / 28, kk = r % 28;
        float val = 0.f;
        if (kk < 25) {
            int cout = q + 4 * kk;
            float s = g2[cout] * rsqrtf(v2[cout] + EPSV);
            val = enc_w[cout * 576 + k] * s;
        }
        g_EWr[idx] = val;
    }
    if (idx < 112) {
        int q = idx / 28, kk = idx % 28;
        float val = 0.f;
        if (kk < 25) {
            int cout = q + 4 * kk;
            float s = g2[cout] * rsqrtf(v2[cout] + EPSV);
            val = s * (enc_b[cout] - m2[cout]) + b2[cout];
        }
        g_bias2r[idx] = val;
    }
}

// ------------------------- K1: 1x1 conv GEMM + bias + relu (f32x2) ----------------
__global__ __launch_bounds__(256) void k1_conv1(const float* __restrict__ X) {
    __shared__ __align__(16) float Xs[16][128];
    __shared__ __align__(16) float Wts[16][64];
    int tid = threadIdx.x;
    int r = tid >> 5;
    int c = tid & 31;
    int b = blockIdx.y;
    int p0 = blockIdx.x * 128;
    const float* Xb = X + (size_t)b * CIN * HL * WL;

    float2 acc2[4][4];
#pragma unroll
    for (int i = 0; i < 4; i++)
#pragma unroll
        for (int j = 0; j < 4; j++) acc2[i][j] = make_float2(0.f, 0.f);

    for (int k0 = 0; k0 < CIN; k0 += 16) {
        __syncthreads();
#pragma unroll
        for (int i = tid; i < 512; i += 256) {
            int kk = i >> 5, pp = (i & 31) * 4;
            *(float4*)&Xs[kk][pp] = *(const float4*)&Xb[(size_t)(k0 + kk) * (HL * WL) + p0 + pp];
        }
        {
            int kk = tid >> 4, co = (tid & 15) * 4;
            *(float4*)&Wts[kk][co] = *(const float4*)&g_WT[(k0 + kk) * CMID + co];
        }
        __syncthreads();
#pragma unroll
        for (int kk = 0; kk < 16; kk++) {
            float2 w2[4]; float x[4];
            *(float4*)&w2[0] = *(float4*)&Wts[kk][r * 8];
            *(float4*)&w2[2] = *(float4*)&Wts[kk][r * 8 + 4];
            *(float4*)&x[0] = *(float4*)&Xs[kk][c * 4];
            float2 xd[4];
#pragma unroll
            for (int j = 0; j < 4; j++) xd[j] = make_float2(x[j], x[j]);
#pragma unroll
            for (int i = 0; i < 4; i++)
#pragma unroll
                for (int j = 0; j < 4; j++) ffma2(acc2[i][j], w2[i], xd[j]);
        }
    }
#pragma unroll
    for (int i = 0; i < 4; i++) {
        int co0 = r * 8 + 2 * i;
        float b0 = g_bias1[co0], b1 = g_bias1[co0 + 1];
        float4 v0, v1;
        v0.x = fmaxf(acc2[i][0].x + b0, 0.f); v0.y = fmaxf(acc2[i][1].x + b0, 0.f);
        v0.z = fmaxf(acc2[i][2].x + b0, 0.f); v0.w = fmaxf(acc2[i][3].x + b0, 0.f);
        v1.x = fmaxf(acc2[i][0].y + b1, 0.f); v1.y = fmaxf(acc2[i][1].y + b1, 0.f);
        v1.z = fmaxf(acc2[i][2].y + b1, 0.f); v1.w = fmaxf(acc2[i][3].y + b1, 0.f);
        *(float4*)&g_W1[((size_t)b * CMID + co0) * (HL * WL) + p0 + c * 4] = v0;
        *(float4*)&g_W1[((size_t)b * CMID + co0 + 1) * (HL * WL) + p0 + c * 4] = v1;
    }
}

// ------------------------- K2: 3x3 conv GEMM + softmax epilogue -------------------
// M=112 x N=128px x K=576, 8-cin chunks (8 iterations). 256 thr: mg 7 couts, ng 8 px.
__global__ __launch_bounds__(256) void k2_kernelpred() {
    __shared__ __align__(16) float smem[9664];   // tin[8][10][20]=1600 + twt[72][112]=8064; epi sL[112][66]=7392
    float* tin = smem;
    float* twt = smem + 1600;

    int tid = threadIdx.x;
    int mg = tid >> 4;
    int ng = tid & 15;
    int py = ng >> 1;
    int px0 = (ng & 1) * 8;
    int b = blockIdx.y;
    int y0 = (blockIdx.x >> 2) * 8;
    int x0 = (blockIdx.x & 3) * 16;

    float2 acc[7][4];
#pragma unroll
    for (int i = 0; i < 7; i++)
#pragma unroll
        for (int j = 0; j < 4; j++) acc[i][j] = make_float2(0.f, 0.f);

    for (int ch = 0; ch < 8; ch++) {
        __syncthreads();
        for (int l = tid; l < 1440; l += 256) {          // stage 8 x 10 x 18 input tile
            int cin = l / 180, rem = l % 180;
            int ty = rem / 18, tx = rem % 18;
            int gy = y0 + ty - 1, gx = x0 + tx - 1;
            float v = 0.f;
            if (gy >= 0 && gy < HL && gx >= 0 && gx < WL)
                v = g_W1[(((size_t)b * CMID + ch * 8 + cin) * HL + gy) * WL + gx];
            tin[cin * 200 + ty * 20 + tx] = v;
        }
        {                                                 // stage 72 x 112 weights
            const float4* src = (const float4*)(g_EWr + ch * 8064);
            float4* dst = (float4*)twt;
            for (int i = tid; i < 2016; i += 256) dst[i] = src[i];
        }
        __syncthreads();
#pragma unroll 2
        for (int cin = 0; cin < 8; cin++)
#pragma unroll
            for (int dy = 0; dy < 3; dy++) {
                const float* rp = &tin[cin * 200 + (py + dy) * 20 + px0];
                float r[10];
                *(float4*)&r[0] = *(const float4*)rp;
                *(float4*)&r[4] = *(const float4*)(rp + 4);
                *(float2*)&r[8] = *(const float2*)(rp + 8);
#pragma unroll
                for (int dx = 0; dx < 3; dx++) {
                    int kl = cin * 9 + dy * 3 + dx;
                    const float* wp = &twt[kl * 112 + mg * 7];
#pragma unroll
                    for (int i = 0; i < 7; i++) {
                        float w = wp[i];
                        float2 w2 = make_float2(w, w);
#pragma unroll
                        for (int j = 0; j < 4; j++) {
                            float2 x2 = make_float2(r[dx + 2 * j], r[dx + 2 * j + 1]);
                            ffma2(acc[i][j], w2, x2);
                        }
                    }
                }
            }
    }

    // epilogue: smem transpose (two x-halves), bias + pixel-shuffle softmax
    float* sL = smem;                                     // [112][66]
    for (int half = 0; half < 2; half++) {
        __syncthreads();
        if ((ng & 1) == half) {
            int colb = py * 8;
#pragma unroll
            for (int i = 0; i < 7; i++) {
                float* row = &sL[(mg * 7 + i) * 66 + colb];
#pragma unroll
                for (int j = 0; j < 4; j++) {
                    row[2 * j] = acc[i][j].x;
                    row[2 * j + 1] = acc[i][j].y;
                }
            }
        }
        __syncthreads();
        {
            int q = tid >> 6;
            int pp = tid & 63;
            int pyy = pp >> 3, pxx = pp & 7;
            int yl = y0 + pyy, xl = x0 + half * 8 + pxx;
            float a[25];
            float mx = -1e30f;
#pragma unroll
            for (int kk = 0; kk < 25; kk++) {
                a[kk] = sL[(q * 28 + kk) * 66 + pp] + __ldg(&g_bias2r[q * 28 + kk]);
                mx = fmaxf(mx, a[kk]);
            }
            float s = 0.f;
#pragma unroll
            for (int kk = 0; kk < 25; kk++) { a[kk] = __expf(a[kk] - mx); s += a[kk]; }
            float inv = 1.0f / s;
            int Y = 2 * yl + (q >> 1), X = 2 * xl + (q & 1);
            float* dst = &g_Wsm[((size_t)(b * HHI + Y) * WHI + X) * 25];
#pragma unroll
            for (int kk = 0; kk < 25; kk++) dst[kk] = a[kk] * inv;
        }
    }
}

// ------------------------- K_bil: bilinear x2 upsample into padded scratch ---------
__global__ __launch_bounds__(256) void k_bilinear(const float* __restrict__ X) {
    int gid = blockIdx.x * 256 + threadIdx.x;
    int xq = gid % 34; int t = gid / 34;
    int yp = t % HP;  t /= HP;
    int c = t % CIN;  int b = t / CIN;
    int y = yp - 4;
    float4 v = make_float4(0.f, 0.f, 0.f, 0.f);
    float* out = &g_Xu[(((size_t)(b * CIN + c) * HP) + yp) * HP + xq * 4];
    if (y >= 0 && y < HHI) {
        int ry = y & 1, yl = y >> 1;
        int ya, yb; float wya, wyb;
        if (ry == 0) { ya = max(yl - 1, 0); yb = yl; wya = 0.25f; wyb = 0.75f; }
        else         { ya = yl; yb = min(yl + 1, HL - 1); wya = 0.75f; wyb = 0.25f; }
        const float* ra = X + ((size_t)(b * CIN + c) * HL + ya) * WL;
        const float* rb = X + ((size_t)(b * CIN + c) * HL + yb) * WL;
        float* vp = (float*)&v;
#pragma unroll
        for (int u = 0; u < 4; u++) {
            int x = xq * 4 + u - 4;
            if (x >= 0 && x < WHI) {
                int rx = x & 1, xl = x >> 1;
                int xa, xb; float wxa, wxb;
                if (rx == 0) { xa = max(xl - 1, 0); xb = xl; wxa = 0.25f; wxb = 0.75f; }
                else         { xa = xl; xb = min(xl + 1, WL - 1); wxa = 0.75f; wxb = 0.25f; }
                vp[u] = wya * (wxa * __ldg(ra + xa) + wxb * __ldg(ra + xb)) +
                        wyb * (wxa * __ldg(rb + xa) + wxb * __ldg(rb + xb));
            }
        }
    }
    *(float4*)out = v;
}

// ------------------------- K3: reassembly, software-pipelined (prefetch c+1) ------
// block 128 thr: 4 rows x 32 quads, grid (32, 8, 4). thread: 4 x-px, 64 channels.
__global__ __launch_bounds__(128) void k3_reassemble(float* __restrict__ out) {
    int tid = threadIdx.x;
    int y = blockIdx.x * 4 + (tid >> 5);
    int x4 = (tid & 31) * 4;
    int b = blockIdx.y;
    int c0 = blockIdx.z * 64;

    float2 wA[25], wB[25];
    const float* wb = &g_Wsm[((size_t)(b * HHI + y) * WHI + x4) * 25];
#pragma unroll
    for (int k = 0; k < 25; k++) {
        wA[k] = make_float2(__ldg(wb + k),      __ldg(wb + 25 + k));
        wB[k] = make_float2(__ldg(wb + 50 + k), __ldg(wb + 75 + k));
    }

    const float* xr = &g_Xu[(((size_t)(b * CIN + c0) * HP) + y) * HP + x4];
    float* ob = out + ((size_t)(b * CIN + c0) * HHI + y) * WHI + x4;
    const size_t chs = (size_t)HP * HP;

    float4 A[5], Bv[5], Cv[5];
#pragma unroll
    for (int i = 0; i < 5; i++) {
        A[i]  = *(const float4*)(xr + 2 * i * HP);
        Bv[i] = *(const float4*)(xr + 2 * i * HP + 4);
        Cv[i] = *(const float4*)(xr + 2 * i * HP + 8);
    }

#pragma unroll 2
    for (int c = 0; c < 64; c++) {
        const float* xn = xr + (c < 63 ? chs : 0);
        float4 An[5], Bn[5], Cn[5];
#pragma unroll
        for (int i = 0; i < 5; i++) {          // prefetch next channel
            An[i] = *(const float4*)(xn + 2 * i * HP);
            Bn[i] = *(const float4*)(xn + 2 * i * HP + 4);
            Cn[i] = *(const float4*)(xn + 2 * i * HP + 8);
        }
        float2 aP0 = make_float2(0.f, 0.f), aP1 = make_float2(0.f, 0.f);
#pragma unroll
        for (int i = 0; i < 5; i++) {
            float2 pr[6] = { make_float2(A[i].x,  A[i].y),  make_float2(A[i].z,  A[i].w),
                             make_float2(Bv[i].x, Bv[i].y), make_float2(Bv[i].z, Bv[i].w),
                             make_float2(Cv[i].x, Cv[i].y), make_float2(Cv[i].z, Cv[i].w) };
#pragma unroll
            for (int j = 0; j < 5; j++) {
                ffma2(aP0, wA[i * 5 + j], pr[j]);
                ffma2(aP1, wB[i * 5 + j], pr[j + 1]);
            }
        }
        *(float4*)ob = make_float4(aP0.x, aP0.y, aP1.x, aP1.y);
        ob += (size_t)HHI * WHI;
        xr = xn;
#pragma unroll
        for (int i = 0; i < 5; i++) { A[i] = An[i]; Bv[i] = Bn[i]; Cv[i] = Cn[i]; }
    }
}

// ------------------------- launch -------------------------
extern "C" void kernel_launch(void* const* d_in, const int* in_sizes, int n_in,
                              void* d_out, int out_size) {
    const float* X      = (const float*)d_in[0];
    const float* comp_w = (const float*)d_in[1];
    const float* comp_b = (const float*)d_in[2];
    const float* bn1_g  = (const float*)d_in[3];
    const float* bn1_b  = (const float*)d_in[4];
    const float* bn1_m  = (const float*)d_in[5];
    const float* bn1_v  = (const float*)d_in[6];
    const float* enc_w  = (const float*)d_in[7];
    const float* enc_b  = (const float*)d_in[8];
    const float* bn2_g  = (const float*)d_in[9];
    const float* bn2_b  = (const float*)d_in[10];
    const float* bn2_m  = (const float*)d_in[11];
    const float* bn2_v  = (const float*)d_in[12];
    float* out = (float*)d_out;

    k0_prep<<<252, 256>>>(comp_w, comp_b, bn1_g, bn1_b, bn1_m, bn1_v,
                          enc_w, enc_b, bn2_g, bn2_b, bn2_m, bn2_v);
    k1_conv1<<<dim3(32, 8), 256>>>(X);
    k_bilinear<<<36992, 256>>>(X);
    k2_kernelpred<<<dim3(32, 8), 256>>>();
    k3_reassemble<<<dim3(32, 8, 4), 128>>>(out);
}

// round 9
// speedup vs baseline: 1.4326x; 1.0729x over previous
#include <cuda_runtime.h>
#include <cuda_fp16.h>
#include <cuda_bf16.h>

#define BB   8
#define CIN  256
#define HL   64
#define WL   64
#define CMID 64
#define HHI  128
#define WHI  128
#define HP   136   // padded hi-res (pad 4 each side)
#define EPSV 1e-5f

// ------------------------- device scratch -------------------------
__device__ float g_WT[CIN * CMID];              // folded transposed 1x1 weights [k][co]
__device__ float g_bias1[CMID];
__device__ float g_EWr[576 * 112];              // folded enc weights [k][m=q*28+kk] (cout=q+4kk)
__device__ float g_bias2r[112];                 // [q*28+kk]
__device__ float g_W1[BB * CMID * HL * WL];     // conv1 output (8,64,64,64)
__device__ float g_Wsm[BB * HHI * WHI * 25];    // softmaxed weights, [b][y][x][25]
__device__ __half g_Xuh[(size_t)BB * CIN * HP * HP]; // padded bilinear upsample (fp16, 75.7MB)

// packed fp32x2 FMA (bit-exact 2x fp32 fma)
__device__ __forceinline__ void ffma2(float2& c, float2 a, float2 b) {
    asm("fma.rn.f32x2 %0, %1, %2, %0;"
        : "+l"(reinterpret_cast<unsigned long long&>(c))
        : "l"(reinterpret_cast<unsigned long long&>(a)),
          "l"(reinterpret_cast<unsigned long long&>(b)));
}

// ------------------------- K0: fold BN into weights -------------------------
__global__ void k0_prep(const float* __restrict__ comp_w, const float* __restrict__ comp_b,
                        const float* __restrict__ g1, const float* __restrict__ b1,
                        const float* __restrict__ m1, const float* __restrict__ v1,
                        const float* __restrict__ enc_w, const float* __restrict__ enc_b,
                        const float* __restrict__ g2, const float* __restrict__ b2,
                        const float* __restrict__ m2, const float* __restrict__ v2) {
    int idx = blockIdx.x * 256 + threadIdx.x;
    if (idx < CIN * CMID) {
        int k = idx / CMID, co = idx % CMID;
        float s = g1[co] * rsqrtf(v1[co] + EPSV);
        g_WT[idx] = comp_w[co * CIN + k] * s;
    }
    if (idx < CMID) {
        float s = g1[idx] * rsqrtf(v1[idx] + EPSV);
        g_bias1[idx] = s * (comp_b[idx] - m1[idx]) + b1[idx];
    }
    if (idx < 576 * 112) {
        int k = idx / 112, r = idx % 112;
        int q = r / 28, kk = r % 28;
        float val = 0.f;
        if (kk < 25) {
            int cout = q + 4 * kk;
            float s = g2[cout] * rsqrtf(v2[cout] + EPSV);
            val = enc_w[cout * 576 + k] * s;
        }
        g_EWr[idx] = val;
    }
    if (idx < 112) {
        int q = idx / 28, kk = idx % 28;
        float val = 0.f;
        if (kk < 25) {
            int cout = q + 4 * kk;
            float s = g2[cout] * rsqrtf(v2[cout] + EPSV);
            val = s * (enc_b[cout] - m2[cout]) + b2[cout];
        }
        g_bias2r[idx] = val;
    }
}

// ------------------------- K1: 1x1 conv GEMM + bias + relu (f32x2) ----------------
__global__ __launch_bounds__(256) void k1_conv1(const float* __restrict__ X) {
    __shared__ __align__(16) float Xs[16][128];
    __shared__ __align__(16) float Wts[16][64];
    int tid = threadIdx.x;
    int r = tid >> 5;
    int c = tid & 31;
    int b = blockIdx.y;
    int p0 = blockIdx.x * 128;
    const float* Xb = X + (size_t)b * CIN * HL * WL;

    float2 acc2[4][4];
#pragma unroll
    for (int i = 0; i < 4; i++)
#pragma unroll
        for (int j = 0; j < 4; j++) acc2[i][j] = make_float2(0.f, 0.f);

    for (int k0 = 0; k0 < CIN; k0 += 16) {
        __syncthreads();
#pragma unroll
        for (int i = tid; i < 512; i += 256) {
            int kk = i >> 5, pp = (i & 31) * 4;
            *(float4*)&Xs[kk][pp] = *(const float4*)&Xb[(size_t)(k0 + kk) * (HL * WL) + p0 + pp];
        }
        {
            int kk = tid >> 4, co = (tid & 15) * 4;
            *(float4*)&Wts[kk][co] = *(const float4*)&g_WT[(k0 + kk) * CMID + co];
        }
        __syncthreads();
#pragma unroll
        for (int kk = 0; kk < 16; kk++) {
            float2 w2[4]; float x[4];
            *(float4*)&w2[0] = *(float4*)&Wts[kk][r * 8];
            *(float4*)&w2[2] = *(float4*)&Wts[kk][r * 8 + 4];
            *(float4*)&x[0] = *(float4*)&Xs[kk][c * 4];
            float2 xd[4];
#pragma unroll
            for (int j = 0; j < 4; j++) xd[j] = make_float2(x[j], x[j]);
#pragma unroll
            for (int i = 0; i < 4; i++)
#pragma unroll
                for (int j = 0; j < 4; j++) ffma2(acc2[i][j], w2[i], xd[j]);
        }
    }
#pragma unroll
    for (int i = 0; i < 4; i++) {
        int co0 = r * 8 + 2 * i;
        float b0 = g_bias1[co0], b1 = g_bias1[co0 + 1];
        float4 v0, v1;
        v0.x = fmaxf(acc2[i][0].x + b0, 0.f); v0.y = fmaxf(acc2[i][1].x + b0, 0.f);
        v0.z = fmaxf(acc2[i][2].x + b0, 0.f); v0.w = fmaxf(acc2[i][3].x + b0, 0.f);
        v1.x = fmaxf(acc2[i][0].y + b1, 0.f); v1.y = fmaxf(acc2[i][1].y + b1, 0.f);
        v1.z = fmaxf(acc2[i][2].y + b1, 0.f); v1.w = fmaxf(acc2[i][3].y + b1, 0.f);
        *(float4*)&g_W1[((size_t)b * CMID + co0) * (HL * WL) + p0 + c * 4] = v0;
        *(float4*)&g_W1[((size_t)b * CMID + co0 + 1) * (HL * WL) + p0 + c * 4] = v1;
    }
}

// ------------------------- K2: 3x3 conv GEMM + softmax epilogue -------------------
// M=112 x N=128px x K=576, 8-cin chunks. 256 thr: mg 7 couts, ng 8 px.
__global__ __launch_bounds__(256, 2) void k2_kernelpred() {
    __shared__ __align__(16) float smem[9664];   // tin[8][10][20]=1600 + twt[72][112]=8064; epi sL[112][66]
    float* tin = smem;
    float* twt = smem + 1600;

    int tid = threadIdx.x;
    int mg = tid >> 4;
    int ng = tid & 15;
    int py = ng >> 1;
    int px0 = (ng & 1) * 8;
    int b = blockIdx.y;
    int y0 = (blockIdx.x >> 2) * 8;
    int x0 = (blockIdx.x & 3) * 16;

    // hoisted staging descriptors (loop-invariant across chunks)
    int soff[6]; int goff[6]; bool inb[6]; bool val[6];
#pragma unroll
    for (int i = 0; i < 6; i++) {
        int l = tid + i * 256;
        inb[i] = (l < 1440);
        int ls = inb[i] ? l : 0;
        int cin = ls / 180, rem = ls % 180;
        int ty = rem / 18, tx = rem % 18;
        int gy = y0 + ty - 1, gx = x0 + tx - 1;
        val[i] = inb[i] && gy >= 0 && gy < HL && gx >= 0 && gx < WL;
        soff[i] = cin * 200 + ty * 20 + tx;
        goff[i] = (cin * HL + gy) * WL + gx;
    }
    const float* w1base = g_W1 + (size_t)b * CMID * HL * WL;

    float2 acc[7][4];
#pragma unroll
    for (int i = 0; i < 7; i++)
#pragma unroll
        for (int j = 0; j < 4; j++) acc[i][j] = make_float2(0.f, 0.f);

    for (int ch = 0; ch < 8; ch++) {
        __syncthreads();
        const float* w1c = w1base + ch * 8 * HL * WL;
#pragma unroll
        for (int i = 0; i < 6; i++) {
            float v = val[i] ? __ldg(w1c + goff[i]) : 0.f;
            if (inb[i]) tin[soff[i]] = v;
        }
        {   // stage 72x112 weights: 2016 float4 = 7 full rounds + tail of 224
            const float4* src = (const float4*)(g_EWr + ch * 8064);
            float4* dst = (float4*)twt;
#pragma unroll
            for (int i = 0; i < 7; i++) dst[tid + i * 256] = src[tid + i * 256];
            if (tid < 224) dst[tid + 1792] = src[tid + 1792];
        }
        __syncthreads();
#pragma unroll 2
        for (int cin = 0; cin < 8; cin++)
#pragma unroll
            for (int dy = 0; dy < 3; dy++) {
                const float* rp = &tin[cin * 200 + (py + dy) * 20 + px0];
                float2 pe[5];
#pragma unroll
                for (int k = 0; k < 5; k++) pe[k] = *(const float2*)(rp + 2 * k);
                float2 po[4];
#pragma unroll
                for (int k = 0; k < 4; k++) po[k] = make_float2(pe[k].y, pe[k + 1].x);
#pragma unroll
                for (int dx = 0; dx < 3; dx++) {
                    int kl = cin * 9 + dy * 3 + dx;
                    const float* wp = &twt[kl * 112 + mg * 7];
                    const float2* P = (dx == 0) ? pe : (dx == 1) ? po : (pe + 1);
#pragma unroll
                    for (int i = 0; i < 7; i++) {
                        float w = wp[i];
                        float2 w2 = make_float2(w, w);
#pragma unroll
                        for (int j = 0; j < 4; j++) ffma2(acc[i][j], w2, P[j]);
                    }
                }
            }
    }

    // epilogue: smem transpose (two x-halves), bias + pixel-shuffle softmax
    float* sL = smem;                                     // [112][66]
    for (int half = 0; half < 2; half++) {
        __syncthreads();
        if ((ng & 1) == half) {
            int colb = py * 8;
#pragma unroll
            for (int i = 0; i < 7; i++) {
                float* row = &sL[(mg * 7 + i) * 66 + colb];
#pragma unroll
                for (int j = 0; j < 4; j++) {
                    row[2 * j] = acc[i][j].x;
                    row[2 * j + 1] = acc[i][j].y;
                }
            }
        }
        __syncthreads();
        {
            int q = tid >> 6;
            int pp = tid & 63;
            int pyy = pp >> 3, pxx = pp & 7;
            int yl = y0 + pyy, xl = x0 + half * 8 + pxx;
            float a[25];
            float mx = -1e30f;
#pragma unroll
            for (int kk = 0; kk < 25; kk++) {
                a[kk] = sL[(q * 28 + kk) * 66 + pp] + __ldg(&g_bias2r[q * 28 + kk]);
                mx = fmaxf(mx, a[kk]);
            }
            float s = 0.f;
#pragma unroll
            for (int kk = 0; kk < 25; kk++) { a[kk] = __expf(a[kk] - mx); s += a[kk]; }
            float inv = 1.0f / s;
            int Y = 2 * yl + (q >> 1), X = 2 * xl + (q & 1);
            float* dst = &g_Wsm[((size_t)(b * HHI + Y) * WHI + X) * 25];
#pragma unroll
            for (int kk = 0; kk < 25; kk++) dst[kk] = a[kk] * inv;
        }
    }
}

// ------------------------- K_bil: bilinear x2 upsample -> fp16 padded scratch -----
__global__ __launch_bounds__(256) void k_bilinear(const float* __restrict__ X) {
    int gid = blockIdx.x * 256 + threadIdx.x;
    int xg = gid % 17; int t = gid / 17;
    int yp = t % HP;  t /= HP;
    int c = t % CIN;  int b = t / CIN;
    int y = yp - 4;
    float v[8];
#pragma unroll
    for (int u = 0; u < 8; u++) v[u] = 0.f;
    if (y >= 0 && y < HHI) {
        int ry = y & 1, yl = y >> 1;
        int ya, yb; float wya, wyb;
        if (ry == 0) { ya = max(yl - 1, 0); yb = yl; wya = 0.25f; wyb = 0.75f; }
        else         { ya = yl; yb = min(yl + 1, HL - 1); wya = 0.75f; wyb = 0.25f; }
        const float* ra = X + ((size_t)(b * CIN + c) * HL + ya) * WL;
        const float* rb = X + ((size_t)(b * CIN + c) * HL + yb) * WL;
#pragma unroll
        for (int u = 0; u < 8; u++) {
            int x = xg * 8 + u - 4;
            if (x >= 0 && x < WHI) {
                int rx = x & 1, xl = x >> 1;
                int xa, xb; float wxa, wxb;
                if (rx == 0) { xa = max(xl - 1, 0); xb = xl; wxa = 0.25f; wxb = 0.75f; }
                else         { xa = xl; xb = min(xl + 1, WL - 1); wxa = 0.75f; wxb = 0.25f; }
                v[u] = wya * (wxa * __ldg(ra + xa) + wxb * __ldg(ra + xb)) +
                       wyb * (wxa * __ldg(rb + xa) + wxb * __ldg(rb + xb));
            }
        }
    }
    __half2 hv[4];
#pragma unroll
    for (int u = 0; u < 4; u++) hv[u] = __floats2half2_rn(v[2 * u], v[2 * u + 1]);
    *(uint4*)&g_Xuh[(((size_t)(b * CIN + c) * HP) + yp) * HP + xg * 8] = *(uint4*)hv;
}

// ------------------------- K3: reassembly (fp16 loads, f32x2 math) ----------------
__global__ __launch_bounds__(128) void k3_reassemble(float* __restrict__ out) {
    int tid = threadIdx.x;
    int y = blockIdx.x * 4 + (tid >> 5);
    int x4 = (tid & 31) * 4;
    int b = blockIdx.y;
    int c0 = blockIdx.z * 64;

    float2 wA[25], wB[25];
    const float* wb = &g_Wsm[((size_t)(b * HHI + y) * WHI + x4) * 25];
#pragma unroll
    for (int k = 0; k < 25; k++) {
        wA[k] = make_float2(__ldg(wb + k),      __ldg(wb + 25 + k));
        wB[k] = make_float2(__ldg(wb + 50 + k), __ldg(wb + 75 + k));
    }

    const __half* xr = &g_Xuh[(((size_t)(b * CIN + c0) * HP) + y) * HP + x4];
    float* ob = out + ((size_t)(b * CIN + c0) * HHI + y) * WHI + x4;
    const size_t chs = (size_t)HP * HP;

    uint2 cur[15], nxt[15];
#pragma unroll
    for (int i = 0; i < 5; i++) {
        const __half* rp = xr + 2 * i * HP;
        cur[3 * i]     = *(const uint2*)(rp);
        cur[3 * i + 1] = *(const uint2*)(rp + 4);
        cur[3 * i + 2] = *(const uint2*)(rp + 8);
    }

#pragma unroll 2
    for (int c = 0; c < 64; c++) {
        const __half* xn = xr + (c < 63 ? chs : 0);
#pragma unroll
        for (int i = 0; i < 5; i++) {
            const __half* rp = xn + 2 * i * HP;
            nxt[3 * i]     = *(const uint2*)(rp);
            nxt[3 * i + 1] = *(const uint2*)(rp + 4);
            nxt[3 * i + 2] = *(const uint2*)(rp + 8);
        }
        float2 aP0 = make_float2(0.f, 0.f), aP1 = make_float2(0.f, 0.f);
#pragma unroll
        for (int i = 0; i < 5; i++) {
            float2 pr[6];
#pragma unroll
            for (int q = 0; q < 3; q++) {
                uint2 rw = cur[3 * i + q];
                pr[2 * q]     = __half22float2(*(const __half2*)&rw.x);
                pr[2 * q + 1] = __half22float2(*(const __half2*)&rw.y);
            }
#pragma unroll
            for (int j = 0; j < 5; j++) {
                ffma2(aP0, wA[i * 5 + j], pr[j]);
                ffma2(aP1, wB[i * 5 + j], pr[j + 1]);
            }
        }
        *(float4*)ob = make_float4(aP0.x, aP0.y, aP1.x, aP1.y);
        ob += (size_t)HHI * WHI;
        xr = xn;
#pragma unroll
        for (int i = 0; i < 15; i++) cur[i] = nxt[i];
    }
}

// ------------------------- launch -------------------------
extern "C" void kernel_launch(void* const* d_in, const int* in_sizes, int n_in,
                              void* d_out, int out_size) {
    const float* X      = (const float*)d_in[0];
    const float* comp_w = (const float*)d_in[1];
    const float* comp_b = (const float*)d_in[2];
    const float* bn1_g  = (const float*)d_in[3];
    const float* bn1_b  = (const float*)d_in[4];
    const float* bn1_m  = (const float*)d_in[5];
    const float* bn1_v  = (const float*)d_in[6];
    const float* enc_w  = (const float*)d_in[7];
    const float* enc_b  = (const float*)d_in[8];
    const float* bn2_g  = (const float*)d_in[9];
    const float* bn2_b  = (const float*)d_in[10];
    const float* bn2_m  = (const float*)d_in[11];
    const float* bn2_v  = (const float*)d_in[12];
    float* out = (float*)d_out;

    k0_prep<<<252, 256>>>(comp_w, comp_b, bn1_g, bn1_b, bn1_m, bn1_v,
                          enc_w, enc_b, bn2_g, bn2_b, bn2_m, bn2_v);
    k1_conv1<<<dim3(32, 8), 256>>>(X);
    k_bilinear<<<18496, 256>>>(X);
    k2_kernelpred<<<dim3(32, 8), 256>>>();
    k3_reassemble<<<dim3(32, 8, 4), 128>>>(out);
}